// round 15
// baseline (speedup 1.0000x reference)
#include <cuda_runtime.h>
#include <cfloat>
#include <cmath>
#include <cstdint>

// ---- problem ----
#define TOKENS 16384
#define HID    4096
#define NEXP   64
#define TOPK   8

// ---- tiling ----
#define MT     128            // tokens per block
#define KC     32             // K per chunk
#define NCH    (HID / KC)     // 128 chunks
#define NTHR   512
#define PIPE   4              // cp.async stages for B
#define STAGEB 8192           // bytes per B chunk stage (2 fp16 splits x 4KB)
#define ABUFB  16384          // bytes per A chunk buffer (2 fp16 splits x 8KB)
// smem: [0,32768) = 4 B-stages, reused as logits; [32768,65536) = 2 A-buffers;
//       bias at 65536
#define SM_A       32768
#define SM_GBS     65536
#define SMEM_BYTES (65536 + 256)

typedef unsigned long long ull;
typedef uint32_t u32;

// pre-split W: byte image of the per-chunk SMEM staging buffer, chunk-major
__device__ __align__(16) unsigned char g_wsplit[(size_t)NCH * STAGEB];   // 1 MB

// ---- PTX helpers (plain-sm_103-safe) ----
__device__ __forceinline__ u32 smem_u32(const void* p) {
    u32 a;
    asm("{ .reg .u64 t; cvta.to.shared.u64 t, %1; cvt.u32.u64 %0, t; }"
        : "=r"(a) : "l"(p));
    return a;
}
__device__ __forceinline__ void ldsm4(u32& r0, u32& r1, u32& r2, u32& r3, u32 a) {
    asm volatile("ldmatrix.sync.aligned.m8n8.x4.shared.b16 {%0,%1,%2,%3}, [%4];"
                 : "=r"(r0), "=r"(r1), "=r"(r2), "=r"(r3) : "r"(a));
}
__device__ __forceinline__ void mma16816(float* c, const u32* a, u32 b0, u32 b1) {
    asm volatile(
        "mma.sync.aligned.m16n8k16.row.col.f32.f16.f16.f32 "
        "{%0,%1,%2,%3}, {%4,%5,%6,%7}, {%8,%9}, {%0,%1,%2,%3};"
        : "+f"(c[0]), "+f"(c[1]), "+f"(c[2]), "+f"(c[3])
        : "r"(a[0]), "r"(a[1]), "r"(a[2]), "r"(a[3]), "r"(b0), "r"(b1));
}
__device__ __forceinline__ void cpasync16(u32 dst, const void* src) {
    asm volatile("cp.async.cg.shared.global [%0], [%1], 16;"
                 :: "r"(dst), "l"(src) : "memory");
}
__device__ __forceinline__ void cp_commit() {
    asm volatile("cp.async.commit_group;" ::: "memory");
}
template <int N>
__device__ __forceinline__ void cp_wait() {
    asm volatile("cp.async.wait_group %0;" :: "n"(N) : "memory");
}

// ---- exact fp32 -> 2x fp16 split (packed, fast-math-immune) ----
__device__ __forceinline__ u32 cvth2(float lo, float hi) {
    u32 r;
    asm("cvt.rn.f16x2.f32 %0, %1, %2;" : "=r"(r) : "f"(hi), "f"(lo));
    return r;   // low half = lo (lower-k element), matches mma packing
}
__device__ __forceinline__ ull expandh(u32 p) {   // f16x2 -> f32x2 (exact)
    ull r;
    asm("{ .reg .b16 x, y; .reg .f32 fx, fy;\n\t"
        "mov.b32 {x, y}, %1;\n\t"
        "cvt.f32.f16 fx, x;\n\t"
        "cvt.f32.f16 fy, y;\n\t"
        "mov.b64 %0, {fx, fy}; }"
        : "=l"(r) : "r"(p));
    return r;
}
__device__ __forceinline__ ull packf2(float lo, float hi) {
    ull r;
    asm("mov.b64 %0, {%1, %2};" : "=l"(r) : "f"(lo), "f"(hi));
    return r;
}
__device__ __forceinline__ void unpackf2(ull v, float& lo, float& hi) {
    asm("mov.b64 {%0, %1}, %2;" : "=f"(lo), "=f"(hi) : "l"(v));
}
__device__ __forceinline__ ull fma2v(ull a, ull b, ull c) {
    ull r;
    asm("fma.rn.f32x2 %0, %1, %2, %3;" : "=l"(r) : "l"(a), "l"(b), "l"(c));
    return r;
}
__device__ __forceinline__ float fadd_rn(float a, float b) {
    float r; asm("add.rn.f32 %0, %1, %2;" : "=f"(r) : "f"(a), "f"(b)); return r;
}
__device__ __forceinline__ float fsub_rn(float a, float b) {
    float r; asm("sub.rn.f32 %0, %1, %2;" : "=f"(r) : "f"(a), "f"(b)); return r;
}
__device__ __forceinline__ void dfadd(float& h, float& l, float v) {
    float t = fadd_rn(h, v);
    float e = fadd_rn(fsub_rn(h, t), v);   // exact when |h| >= |v|
    l = fadd_rn(l, e);
    h = t;
}
// v -> q0 = f16x2(v), q1 = f16x2(v - f32(q0));  residual ~2^-22 |v| dropped
__device__ __forceinline__ void split1f(float vlo, float vhi, ull neg1,
                                        u32& q0, u32& q1) {
    ull v = packf2(vlo, vhi);
    q0 = cvth2(vlo, vhi);
    ull r1 = fma2v(expandh(q0), neg1, v);      // v - (f32)q0, exact
    float rl, rh; unpackf2(r1, rl, rh);
    q1 = cvth2(rl, rh);
}

// ---- pre-pass: split W once into the SMEM byte-image layout ----
__global__ __launch_bounds__(256)
void wsplit_kernel(const float* __restrict__ gw)
{
    const int c   = blockIdx.x;          // chunk
    const int tid = threadIdx.x;
    const int bn  = tid >> 2;            // expert 0..63
    const int bkt = tid & 3;             // k-tile 0..3
    const float* wp = gw + (size_t)bn * HID + c * KC + bkt * 8;
    const float4 w0 = *(const float4*)(wp);
    const float4 w1 = *(const float4*)(wp + 4);
    const ull NEG1 = packf2(-1.0f, -1.0f);
    u32 s0[4], s1[4];
    split1f(w0.x, w0.y, NEG1, s0[0], s1[0]);
    split1f(w0.z, w0.w, NEG1, s0[1], s1[1]);
    split1f(w1.x, w1.y, NEG1, s0[2], s1[2]);
    split1f(w1.z, w1.w, NEG1, s0[3], s1[3]);
    const int bst = (((bn >> 3) * 4 + bkt) * 8 + ((bn & 7) ^ bkt)) * 16;
    unsigned char* dst = g_wsplit + (size_t)c * STAGEB + bst;
    *(uint4*)(dst)        = make_uint4(s0[0], s0[1], s0[2], s0[3]);
    *(uint4*)(dst + 4096) = make_uint4(s1[0], s1[1], s1[2], s1[3]);
}

__global__ __launch_bounds__(NTHR, 1)
void gating_kernel(const float* __restrict__ x,
                   const float* __restrict__ gb,
                   float* __restrict__ out)
{
    extern __shared__ __align__(16) char sm[];
    float* lg  = (float*)sm;                 // logits, reuses B stages
    float* gbs = (float*)(sm + SM_GBS);      // bias
    const u32 sb = smem_u32(sm);

    const int tid  = threadIdx.x;
    const int wid  = tid >> 5;
    const int lane = tid & 31;
    const int m0   = blockIdx.x * MT;
    const int half = wid & 1;                // n-half: cols [32*half, 32*half+32)
    const int mw   = wid >> 1;               // row strip: rows [16*mw, 16*mw+16)

    if (tid < NEXP) gbs[tid] = gb[tid];

    const ull NEG1 = packf2(-1.0f, -1.0f);

    // ---- A conversion mapping: thread -> (row = tid/4, k-tile = tid%4) ----
    const int arow = tid >> 2;               // 0..127
    const int akt  = tid & 3;                // 0..3
    const float* axp = x + (size_t)(m0 + arow) * HID + akt * 8;
    // tile-image offset (same scheme as B): 8x8 fp16 tiles, row rotation r^kt
    const int ast = (((arow >> 3) * 4 + akt) * 8 + ((arow & 7) ^ akt)) * 16;

    // ---- cp.async mapping: each thread copies 16B of the 8KB B stage ----
    const u32 wdoff = (u32)(tid * 16);
    const unsigned char* wsrc = g_wsplit + tid * 16;

    // ---- accumulators: 4 n-tiles x 4 regs ----
    float ah[4][4], al[4][4], aM[4][4], aC[4][4];
#pragma unroll
    for (int i = 0; i < 4; i++)
#pragma unroll
        for (int j = 0; j < 4; j++) { ah[i][j] = 0.f; al[i][j] = 0.f; aM[i][j] = 0.f; aC[i][j] = 0.f; }

    // ---- prologue: issue B stages 0..PIPE-2 ----
#pragma unroll
    for (int p = 0; p < PIPE - 1; p++) {
        cpasync16(sb + p * STAGEB + wdoff, wsrc + (size_t)p * STAGEB);
        cp_commit();
    }

    // ---- A prefetch chunk 0 (coalesced float4) ----
    float4 xc[2], xn[2];
    xc[0] = *(const float4*)(axp);
    xc[1] = *(const float4*)(axp + 4);

    const int g = lane >> 3, rsw = lane & 7;   // ldmatrix lane-group / row
    // A ldsm per-lane tile coordinates (fixed parts)
    const int a_rowblk = 2 * mw + (g & 1);     // 0..15
    const int a_kthl   = g >> 1;               // k16-half selector

    // ---- chunk body (cur/nxt A register sets alternate) ----
    auto body = [&](int c, float4 (&cx)[2], float4 (&nx)[2]) {
        // 1) convert A chunk c -> tile-image SMEM (split once per element)
        {
            u32 s0[4], s1[4];
            split1f(cx[0].x, cx[0].y, NEG1, s0[0], s1[0]);
            split1f(cx[0].z, cx[0].w, NEG1, s0[1], s1[1]);
            split1f(cx[1].x, cx[1].y, NEG1, s0[2], s1[2]);
            split1f(cx[1].z, cx[1].w, NEG1, s0[3], s1[3]);
            char* p = sm + SM_A + (c & 1) * ABUFB + ast;
            *(uint4*)(p)        = make_uint4(s0[0], s0[1], s0[2], s0[3]);
            *(uint4*)(p + 8192) = make_uint4(s1[0], s1[1], s1[2], s1[3]);
        }

        // 2) B stage c complete + A buffer visible block-wide
        cp_wait<PIPE - 2>();
        __syncthreads();

        // 3) refill B stage (empty commit keeps wait_group arithmetic exact)
        const int cf = c + PIPE - 1;
        if (cf < NCH)
            cpasync16(sb + (cf & (PIPE - 1)) * STAGEB + wdoff,
                      wsrc + (size_t)cf * STAGEB);
        cp_commit();

        //    A LDGs for next chunk (latency hidden under mma)
        const int cn = (c + 1 < NCH) ? (c + 1) * KC : 0;
        nx[0] = *(const float4*)(axp + cn);
        nx[1] = *(const float4*)(axp + cn + 4);

        // 4) mma phase on B stage c%PIPE, A buffer c%2
        const u32 bb = sb + (c & (PIPE - 1)) * STAGEB;
        const u32 ab = sb + SM_A + (c & 1) * ABUFB;

#pragma unroll
        for (int s = 0; s < 2; s++) {
            // A fragments via ldsm (both splits)
            const int akt2 = 2 * s + a_kthl;
            const u32 aad = ab + (u32)(((a_rowblk * 4 + akt2) * 8 + (rsw ^ akt2)) * 16);
            u32 a0[4], a1[4];
            ldsm4(a0[0], a0[1], a0[2], a0[3], aad);
            ldsm4(a1[0], a1[1], a1[2], a1[3], aad + 8192);

            const int kt = s * 2 + (g & 1);
            u32 ad[2];
#pragma unroll
            for (int tp = 0; tp < 2; tp++) {
                const int tn = half * 4 + tp * 2 + (g >> 1);
                ad[tp] = bb + (u32)(((tn * 4 + kt) * 8 + (rsw ^ kt)) * 16);
            }

            u32 b[2][4];
            // split0: a0*b0 -> M, a1*b0 -> C
#pragma unroll
            for (int tp = 0; tp < 2; tp++)
                ldsm4(b[tp][0], b[tp][1], b[tp][2], b[tp][3], ad[tp]);
#pragma unroll
            for (int tp = 0; tp < 2; tp++)
#pragma unroll
                for (int t2 = 0; t2 < 2; t2++)
                    mma16816(aM[tp * 2 + t2], a0, b[tp][2 * t2], b[tp][2 * t2 + 1]);
#pragma unroll
            for (int tp = 0; tp < 2; tp++)
#pragma unroll
                for (int t2 = 0; t2 < 2; t2++)
                    mma16816(aC[tp * 2 + t2], a1, b[tp][2 * t2], b[tp][2 * t2 + 1]);

            // split1: a0*b1 -> C
#pragma unroll
            for (int tp = 0; tp < 2; tp++)
                ldsm4(b[tp][0], b[tp][1], b[tp][2], b[tp][3], ad[tp] + 4096);
#pragma unroll
            for (int tp = 0; tp < 2; tp++)
#pragma unroll
                for (int t2 = 0; t2 < 2; t2++)
                    mma16816(aC[tp * 2 + t2], a0, b[tp][2 * t2], b[tp][2 * t2 + 1]);
        }

        // 5) Fast2Sum flush of main accumulator every 2 chunks (K=64)
        if (c & 1) {
#pragma unroll
            for (int i = 0; i < 4; i++)
#pragma unroll
                for (int j = 0; j < 4; j++) {
                    dfadd(ah[i][j], al[i][j], aM[i][j]);
                    aM[i][j] = 0.f;
                }
        }
    };

#pragma unroll 1
    for (int c = 0; c < NCH; c += 2) {
        body(c,     xc, xn);
        body(c + 1, xn, xc);
    }

    __syncthreads();   // all mma reads of B/A regions done before logits overwrite

    // ---- logits = ah + (al + corrections) + bias -> smem ----
    {
        const int row0 = mw * 16 + (lane >> 2);
#pragma unroll
        for (int t = 0; t < 4; t++)
#pragma unroll
            for (int k = 0; k < 4; k++) {
                int row = row0 + ((k >> 1) ? 8 : 0);
                int col = half * 32 + t * 8 + (lane & 3) * 2 + (k & 1);
                float v = fadd_rn(ah[t][k], fadd_rn(al[t][k], aC[t][k]));
                lg[row * NEXP + col] = fadd_rn(v, gbs[col]);
            }
    }
    __syncthreads();

    // ---- top-8 + softmax: one warp per token ----
    const unsigned FULL = 0xffffffffu;
    float* outw = out;
    float* outi = out + (size_t)TOKENS * TOPK;

    for (int t = wid; t < MT; t += 16) {
        float v0 = lg[t * NEXP + lane];
        float v1 = lg[t * NEXP + lane + 32];
        int   i0 = lane, i1 = lane + 32;

        float m = 0.f, ssum = 0.f, myv = 0.f;
        int myi = 0;

#pragma unroll
        for (int s = 0; s < TOPK; s++) {
            float v; int idx;
            if (v0 > v1 || (v0 == v1 && i0 < i1)) { v = v0; idx = i0; }
            else                                  { v = v1; idx = i1; }
#pragma unroll
            for (int off = 16; off > 0; off >>= 1) {
                float ov = __shfl_down_sync(FULL, v,   off);
                int   oi = __shfl_down_sync(FULL, idx, off);
                if (ov > v || (ov == v && oi < idx)) { v = ov; idx = oi; }
            }
            v   = __shfl_sync(FULL, v,   0);
            idx = __shfl_sync(FULL, idx, 0);

            if (s == 0) m = v;               // max (sorted descending)
            ssum += expf(v - m);
            if (lane == s) { myv = v; myi = idx; }

            if (idx == i0) v0 = -FLT_MAX;
            if (idx == i1) v1 = -FLT_MAX;
        }

        if (lane < TOPK) {
            int gidx = (m0 + t) * TOPK + lane;
            outw[gidx] = expf(myv - m) / ssum;
            outi[gidx] = (float)myi;
        }
    }
}

extern "C" void kernel_launch(void* const* d_in, const int* in_sizes, int n_in,
                              void* d_out, int out_size)
{
    const float* x  = (const float*)d_in[0];   // (16384, 4096) f32
    const float* gw = (const float*)d_in[1];   // (64, 4096)    f32
    const float* gb = (const float*)d_in[2];   // (64,)         f32
    float* out = (float*)d_out;                // [weights | indices] as f32

    cudaFuncSetAttribute(gating_kernel,
                         cudaFuncAttributeMaxDynamicSharedMemorySize, SMEM_BYTES);
    wsplit_kernel<<<NCH, 256>>>(gw);
    gating_kernel<<<TOKENS / MT, NTHR, SMEM_BYTES>>>(x, gb, out);
}

// round 16
// speedup vs baseline: 1.3237x; 1.3237x over previous
#include <cuda_runtime.h>
#include <cfloat>
#include <cmath>
#include <cstdint>

// ---- problem ----
#define TOKENS 16384
#define HID    4096
#define NEXP   64
#define TOPK   8

// ---- tiling ----
#define MT     64             // tokens per block (2 CTAs/SM co-residency)
#define KC     32             // K per chunk
#define NCH    (HID / KC)     // 128 chunks
#define NTHR   256
#define PIPE   4              // cp.async stages
#define STAGEB 8192           // bytes per chunk stage (2 fp16 splits x 4KB)
// smem: [0, 32768) = 4 B-stages (32KB) reused as logits (16KB); bias at 32768
#define SMEM_BYTES (32768 + 256)

typedef unsigned long long ull;
typedef uint32_t u32;

// pre-split W: byte image of the per-chunk SMEM staging buffer, chunk-major
__device__ __align__(16) unsigned char g_wsplit[(size_t)NCH * STAGEB];   // 1 MB

// ---- PTX helpers (plain-sm_103-safe) ----
__device__ __forceinline__ u32 smem_u32(const void* p) {
    u32 a;
    asm("{ .reg .u64 t; cvta.to.shared.u64 t, %1; cvt.u32.u64 %0, t; }"
        : "=r"(a) : "l"(p));
    return a;
}
__device__ __forceinline__ void ldsm4(u32& r0, u32& r1, u32& r2, u32& r3, u32 a) {
    asm volatile("ldmatrix.sync.aligned.m8n8.x4.shared.b16 {%0,%1,%2,%3}, [%4];"
                 : "=r"(r0), "=r"(r1), "=r"(r2), "=r"(r3) : "r"(a));
}
__device__ __forceinline__ void mma16816(float* c, const u32* a, u32 b0, u32 b1) {
    asm volatile(
        "mma.sync.aligned.m16n8k16.row.col.f32.f16.f16.f32 "
        "{%0,%1,%2,%3}, {%4,%5,%6,%7}, {%8,%9}, {%0,%1,%2,%3};"
        : "+f"(c[0]), "+f"(c[1]), "+f"(c[2]), "+f"(c[3])
        : "r"(a[0]), "r"(a[1]), "r"(a[2]), "r"(a[3]), "r"(b0), "r"(b1));
}
__device__ __forceinline__ void cpasync16(u32 dst, const void* src) {
    asm volatile("cp.async.cg.shared.global [%0], [%1], 16;"
                 :: "r"(dst), "l"(src) : "memory");
}
__device__ __forceinline__ void cp_commit() {
    asm volatile("cp.async.commit_group;" ::: "memory");
}
template <int N>
__device__ __forceinline__ void cp_wait() {
    asm volatile("cp.async.wait_group %0;" :: "n"(N) : "memory");
}

// ---- exact fp32 -> 2x fp16 split (packed, fast-math-immune) ----
__device__ __forceinline__ u32 cvth2(float lo, float hi) {
    u32 r;
    asm("cvt.rn.f16x2.f32 %0, %1, %2;" : "=r"(r) : "f"(hi), "f"(lo));
    return r;   // low half = lo (lower-k element), matches mma packing
}
__device__ __forceinline__ ull expandh(u32 p) {   // f16x2 -> f32x2 (exact)
    ull r;
    asm("{ .reg .b16 x, y; .reg .f32 fx, fy;\n\t"
        "mov.b32 {x, y}, %1;\n\t"
        "cvt.f32.f16 fx, x;\n\t"
        "cvt.f32.f16 fy, y;\n\t"
        "mov.b64 %0, {fx, fy}; }"
        : "=l"(r) : "r"(p));
    return r;
}
__device__ __forceinline__ ull packf2(float lo, float hi) {
    ull r;
    asm("mov.b64 %0, {%1, %2};" : "=l"(r) : "f"(lo), "f"(hi));
    return r;
}
__device__ __forceinline__ void unpackf2(ull v, float& lo, float& hi) {
    asm("mov.b64 {%0, %1}, %2;" : "=f"(lo), "=f"(hi) : "l"(v));
}
__device__ __forceinline__ ull fma2v(ull a, ull b, ull c) {
    ull r;
    asm("fma.rn.f32x2 %0, %1, %2, %3;" : "=l"(r) : "l"(a), "l"(b), "l"(c));
    return r;
}
__device__ __forceinline__ float fadd_rn(float a, float b) {
    float r; asm("add.rn.f32 %0, %1, %2;" : "=f"(r) : "f"(a), "f"(b)); return r;
}
__device__ __forceinline__ float fsub_rn(float a, float b) {
    float r; asm("sub.rn.f32 %0, %1, %2;" : "=f"(r) : "f"(a), "f"(b)); return r;
}
__device__ __forceinline__ void dfadd(float& h, float& l, float v) {
    float t = fadd_rn(h, v);
    float e = fadd_rn(fsub_rn(h, t), v);   // exact when |h| >= |v|
    l = fadd_rn(l, e);
    h = t;
}
// v -> q0 = f16x2(v), q1 = f16x2(v - f32(q0));  residual ~2^-22 |v| dropped
__device__ __forceinline__ void split1f(float vlo, float vhi, ull neg1,
                                        u32& q0, u32& q1) {
    ull v = packf2(vlo, vhi);
    q0 = cvth2(vlo, vhi);
    ull r1 = fma2v(expandh(q0), neg1, v);      // v - (f32)q0, exact
    float rl, rh; unpackf2(r1, rl, rh);
    q1 = cvth2(rl, rh);
}

// ---- pre-pass: split W once into the SMEM byte-image layout ----
__global__ __launch_bounds__(256)
void wsplit_kernel(const float* __restrict__ gw)
{
    const int c   = blockIdx.x;          // chunk
    const int tid = threadIdx.x;
    const int bn  = tid >> 2;            // expert 0..63
    const int bkt = tid & 3;             // k-tile 0..3
    const float* wp = gw + (size_t)bn * HID + c * KC + bkt * 8;
    const float4 w0 = *(const float4*)(wp);
    const float4 w1 = *(const float4*)(wp + 4);
    const ull NEG1 = packf2(-1.0f, -1.0f);
    u32 s0[4], s1[4];
    split1f(w0.x, w0.y, NEG1, s0[0], s1[0]);
    split1f(w0.z, w0.w, NEG1, s0[1], s1[1]);
    split1f(w1.x, w1.y, NEG1, s0[2], s1[2]);
    split1f(w1.z, w1.w, NEG1, s0[3], s1[3]);
    const int bst = (((bn >> 3) * 4 + bkt) * 8 + ((bn & 7) ^ bkt)) * 16;
    unsigned char* dst = g_wsplit + (size_t)c * STAGEB + bst;
    *(uint4*)(dst)        = make_uint4(s0[0], s0[1], s0[2], s0[3]);
    *(uint4*)(dst + 4096) = make_uint4(s1[0], s1[1], s1[2], s1[3]);
}

__global__ __launch_bounds__(NTHR, 2)
void gating_kernel(const float* __restrict__ x,
                   const float* __restrict__ gb,
                   float* __restrict__ out)
{
    __shared__ __align__(16) char sm[SMEM_BYTES];
    float* lg  = (float*)sm;                 // logits, reuses B stages
    float* gbs = (float*)(sm + 32768);       // bias
    const u32 sb = smem_u32(sm);

    const int tid  = threadIdx.x;
    const int wid  = tid >> 5;
    const int lane = tid & 31;
    const int m0   = blockIdx.x * MT;
    const int half = wid & 1;                // n-half: cols [32*half, 32*half+32)
    const int mw   = wid >> 1;               // row strip: rows [16*mw, 16*mw+16)

    if (tid < NEXP) gbs[tid] = gb[tid];

    const ull NEG1 = packf2(-1.0f, -1.0f);

    // ---- per-thread A source addresses (direct global -> register) ----
    const int ar = m0 + mw * 16 + (lane >> 2);
    const float* xp0 = x + (size_t)ar * HID + (lane & 3) * 2;
    const float* xp1 = xp0 + (size_t)8 * HID;

    // ---- cp.async mapping: each thread copies 2x16B of the 8KB stage ----
    const u32 wdoff = (u32)(tid * 16);
    const unsigned char* wsrc = g_wsplit + tid * 16;

    // ---- accumulators: 4 n-tiles x 4 regs ----
    float ah[4][4], al[4][4], aM[4][4], aC[4][4];
#pragma unroll
    for (int i = 0; i < 4; i++)
#pragma unroll
        for (int j = 0; j < 4; j++) { ah[i][j] = 0.f; al[i][j] = 0.f; aM[i][j] = 0.f; aC[i][j] = 0.f; }

    // ---- prologue: issue B stages 0..PIPE-2 ----
#pragma unroll
    for (int p = 0; p < PIPE - 1; p++) {
        cpasync16(sb + p * STAGEB + wdoff, wsrc + (size_t)p * STAGEB);
        cpasync16(sb + p * STAGEB + wdoff + 4096,
                  wsrc + (size_t)p * STAGEB + 4096);
        cp_commit();
    }

    // ---- A prefetch chunk 0 ----
    float2 xc[2][2][2], xn[2][2][2];   // [row01][kstep][khalf]
#pragma unroll
    for (int s = 0; s < 2; s++)
#pragma unroll
        for (int u = 0; u < 2; u++) {
            xc[0][s][u] = *(const float2*)(xp0 + s * 16 + u * 8);
            xc[1][s][u] = *(const float2*)(xp1 + s * 16 + u * 8);
        }

    const int g = lane >> 3, rsw = lane & 7;   // ldmatrix lane-group / row

    // ---- chunk body (cur/nxt A register sets alternate; no rotation MOVs) ----
    auto body = [&](int c, float2 (&cx)[2][2][2], float2 (&nx)[2][2][2]) {
        // chunk c's B group complete (pending <= PIPE-2), then block-wide visibility
        cp_wait<PIPE - 2>();
        __syncthreads();

        // refill freed stage (empty commit keeps wait_group arithmetic exact)
        const int cf = c + PIPE - 1;
        if (cf < NCH) {
            cpasync16(sb + (cf & (PIPE - 1)) * STAGEB + wdoff,
                      wsrc + (size_t)cf * STAGEB);
            cpasync16(sb + (cf & (PIPE - 1)) * STAGEB + wdoff + 4096,
                      wsrc + (size_t)cf * STAGEB + 4096);
        }
        cp_commit();

        // A LDGs for next chunk (latency hidden under mma)
        const int cn = (c + 1 < NCH) ? (c + 1) * KC : 0;
#pragma unroll
        for (int s = 0; s < 2; s++)
#pragma unroll
            for (int u = 0; u < 2; u++) {
                nx[0][s][u] = *(const float2*)(xp0 + cn + s * 16 + u * 8);
                nx[1][s][u] = *(const float2*)(xp1 + cn + s * 16 + u * 8);
            }

        // ---- mma phase on stage c%PIPE ----
        const u32 bb = sb + (c & (PIPE - 1)) * STAGEB;

#pragma unroll
        for (int s = 0; s < 2; s++) {
            // A splits for this k16-step
            u32 af0[4], af1[4];
            split1f(cx[0][s][0].x, cx[0][s][0].y, NEG1, af0[0], af1[0]);
            split1f(cx[1][s][0].x, cx[1][s][0].y, NEG1, af0[1], af1[1]);
            split1f(cx[0][s][1].x, cx[0][s][1].y, NEG1, af0[2], af1[2]);
            split1f(cx[1][s][1].x, cx[1][s][1].y, NEG1, af0[3], af1[3]);

            const int kt = s * 2 + (g & 1);
            u32 ad[2];
#pragma unroll
            for (int tp = 0; tp < 2; tp++) {
                const int tn = half * 4 + tp * 2 + (g >> 1);
                ad[tp] = bb + (u32)(((tn * 4 + kt) * 8 + (rsw ^ kt)) * 16);
            }

            u32 b[2][4];
            // split0: a0*b0 -> M, a1*b0 -> C
#pragma unroll
            for (int tp = 0; tp < 2; tp++)
                ldsm4(b[tp][0], b[tp][1], b[tp][2], b[tp][3], ad[tp]);
#pragma unroll
            for (int tp = 0; tp < 2; tp++)
#pragma unroll
                for (int t2 = 0; t2 < 2; t2++)
                    mma16816(aM[tp * 2 + t2], af0, b[tp][2 * t2], b[tp][2 * t2 + 1]);
#pragma unroll
            for (int tp = 0; tp < 2; tp++)
#pragma unroll
                for (int t2 = 0; t2 < 2; t2++)
                    mma16816(aC[tp * 2 + t2], af1, b[tp][2 * t2], b[tp][2 * t2 + 1]);

            // split1: a0*b1 -> C
#pragma unroll
            for (int tp = 0; tp < 2; tp++)
                ldsm4(b[tp][0], b[tp][1], b[tp][2], b[tp][3], ad[tp] + 4096);
#pragma unroll
            for (int tp = 0; tp < 2; tp++)
#pragma unroll
                for (int t2 = 0; t2 < 2; t2++)
                    mma16816(aC[tp * 2 + t2], af0, b[tp][2 * t2], b[tp][2 * t2 + 1]);
        }

        // Fast2Sum flush of main accumulator every 2 chunks (K=64)
        if (c & 1) {
#pragma unroll
            for (int i = 0; i < 4; i++)
#pragma unroll
                for (int j = 0; j < 4; j++) {
                    dfadd(ah[i][j], al[i][j], aM[i][j]);
                    aM[i][j] = 0.f;
                }
        }
    };

#pragma unroll 1
    for (int c = 0; c < NCH; c += 2) {
        body(c,     xc, xn);
        body(c + 1, xn, xc);
    }

    __syncthreads();   // all mma reads of B stages done before logits overwrite

    // ---- logits = ah + (al + corrections) + bias -> smem ----
    {
        const int row0 = mw * 16 + (lane >> 2);
#pragma unroll
        for (int t = 0; t < 4; t++)
#pragma unroll
            for (int k = 0; k < 4; k++) {
                int row = row0 + ((k >> 1) ? 8 : 0);
                int col = half * 32 + t * 8 + (lane & 3) * 2 + (k & 1);
                float v = fadd_rn(ah[t][k], fadd_rn(al[t][k], aC[t][k]));
                lg[row * NEXP + col] = fadd_rn(v, gbs[col]);
            }
    }
    __syncthreads();

    // ---- top-8 + softmax: one warp per token ----
    const unsigned FULL = 0xffffffffu;
    float* outw = out;
    float* outi = out + (size_t)TOKENS * TOPK;

    for (int t = wid; t < MT; t += 8) {
        float v0 = lg[t * NEXP + lane];
        float v1 = lg[t * NEXP + lane + 32];
        int   i0 = lane, i1 = lane + 32;

        float m = 0.f, ssum = 0.f, myv = 0.f;
        int myi = 0;

#pragma unroll
        for (int s = 0; s < TOPK; s++) {
            float v; int idx;
            if (v0 > v1 || (v0 == v1 && i0 < i1)) { v = v0; idx = i0; }
            else                                  { v = v1; idx = i1; }
#pragma unroll
            for (int off = 16; off > 0; off >>= 1) {
                float ov = __shfl_down_sync(FULL, v,   off);
                int   oi = __shfl_down_sync(FULL, idx, off);
                if (ov > v || (ov == v && oi < idx)) { v = ov; idx = oi; }
            }
            v   = __shfl_sync(FULL, v,   0);
            idx = __shfl_sync(FULL, idx, 0);

            if (s == 0) m = v;               // max (sorted descending)
            ssum += expf(v - m);
            if (lane == s) { myv = v; myi = idx; }

            if (idx == i0) v0 = -FLT_MAX;
            if (idx == i1) v1 = -FLT_MAX;
        }

        if (lane < TOPK) {
            int gidx = (m0 + t) * TOPK + lane;
            outw[gidx] = expf(myv - m) / ssum;
            outi[gidx] = (float)myi;
        }
    }
}

extern "C" void kernel_launch(void* const* d_in, const int* in_sizes, int n_in,
                              void* d_out, int out_size)
{
    const float* x  = (const float*)d_in[0];   // (16384, 4096) f32
    const float* gw = (const float*)d_in[1];   // (64, 4096)    f32
    const float* gb = (const float*)d_in[2];   // (64,)         f32
    float* out = (float*)d_out;                // [weights | indices] as f32

    wsplit_kernel<<<NCH, 256>>>(gw);
    gating_kernel<<<TOKENS / MT, NTHR>>>(x, gb, out);
}

// round 17
// speedup vs baseline: 1.6232x; 1.2262x over previous
#include <cuda_runtime.h>
#include <cfloat>
#include <cmath>
#include <cstdint>

// ---- problem ----
#define TOKENS 16384
#define HID    4096
#define NEXP   64
#define TOPK   8

// ---- tiling ----
#define MT     128            // tokens per block
#define KC     32             // K per chunk
#define NCH    (HID / KC)     // 128 chunks
#define NTHR   512
#define PIPE   4              // cp.async stages
#define BOFF   0              // B split tiles within stage (8KB)
#define AOFF   8192           // A fp32 rows within stage (16KB)
#define STAGEB 24576          // 8KB B + 16KB A
#define SM_GBS (PIPE * STAGEB)             // bias after stages
#define SMEM_BYTES (SM_GBS + 256)          // 98560

typedef unsigned long long ull;
typedef uint32_t u32;

// pre-split W: byte image of the per-chunk B stage region, chunk-major
__device__ __align__(16) unsigned char g_wsplit[(size_t)NCH * 8192];   // 1 MB

// ---- PTX helpers (plain-sm_103-safe) ----
__device__ __forceinline__ u32 smem_u32(const void* p) {
    u32 a;
    asm("{ .reg .u64 t; cvta.to.shared.u64 t, %1; cvt.u32.u64 %0, t; }"
        : "=r"(a) : "l"(p));
    return a;
}
__device__ __forceinline__ void ldsm4(u32& r0, u32& r1, u32& r2, u32& r3, u32 a) {
    asm volatile("ldmatrix.sync.aligned.m8n8.x4.shared.b16 {%0,%1,%2,%3}, [%4];"
                 : "=r"(r0), "=r"(r1), "=r"(r2), "=r"(r3) : "r"(a));
}
__device__ __forceinline__ void mma16816(float* c, const u32* a, u32 b0, u32 b1) {
    asm volatile(
        "mma.sync.aligned.m16n8k16.row.col.f32.f16.f16.f32 "
        "{%0,%1,%2,%3}, {%4,%5,%6,%7}, {%8,%9}, {%0,%1,%2,%3};"
        : "+f"(c[0]), "+f"(c[1]), "+f"(c[2]), "+f"(c[3])
        : "r"(a[0]), "r"(a[1]), "r"(a[2]), "r"(a[3]), "r"(b0), "r"(b1));
}
__device__ __forceinline__ void cpasync16(u32 dst, const void* src) {
    asm volatile("cp.async.cg.shared.global [%0], [%1], 16;"
                 :: "r"(dst), "l"(src) : "memory");
}
__device__ __forceinline__ void cp_commit() {
    asm volatile("cp.async.commit_group;" ::: "memory");
}
template <int N>
__device__ __forceinline__ void cp_wait() {
    asm volatile("cp.async.wait_group %0;" :: "n"(N) : "memory");
}
__device__ __forceinline__ float2 lds64(u32 a) {
    float2 v;
    asm volatile("ld.shared.v2.f32 {%0, %1}, [%2];"
                 : "=f"(v.x), "=f"(v.y) : "r"(a));
    return v;
}

// ---- exact fp32 -> 2x fp16 split (packed, fast-math-immune) ----
__device__ __forceinline__ u32 cvth2(float lo, float hi) {
    u32 r;
    asm("cvt.rn.f16x2.f32 %0, %1, %2;" : "=r"(r) : "f"(hi), "f"(lo));
    return r;   // low half = lo (lower-k element), matches mma packing
}
__device__ __forceinline__ ull expandh(u32 p) {   // f16x2 -> f32x2 (exact)
    ull r;
    asm("{ .reg .b16 x, y; .reg .f32 fx, fy;\n\t"
        "mov.b32 {x, y}, %1;\n\t"
        "cvt.f32.f16 fx, x;\n\t"
        "cvt.f32.f16 fy, y;\n\t"
        "mov.b64 %0, {fx, fy}; }"
        : "=l"(r) : "r"(p));
    return r;
}
__device__ __forceinline__ ull packf2(float lo, float hi) {
    ull r;
    asm("mov.b64 %0, {%1, %2};" : "=l"(r) : "f"(lo), "f"(hi));
    return r;
}
__device__ __forceinline__ void unpackf2(ull v, float& lo, float& hi) {
    asm("mov.b64 {%0, %1}, %2;" : "=f"(lo), "=f"(hi) : "l"(v));
}
__device__ __forceinline__ ull fma2v(ull a, ull b, ull c) {
    ull r;
    asm("fma.rn.f32x2 %0, %1, %2, %3;" : "=l"(r) : "l"(a), "l"(b), "l"(c));
    return r;
}
__device__ __forceinline__ float fadd_rn(float a, float b) {
    float r; asm("add.rn.f32 %0, %1, %2;" : "=f"(r) : "f"(a), "f"(b)); return r;
}
__device__ __forceinline__ float fsub_rn(float a, float b) {
    float r; asm("sub.rn.f32 %0, %1, %2;" : "=f"(r) : "f"(a), "f"(b)); return r;
}
__device__ __forceinline__ void dfadd(float& h, float& l, float v) {
    float t = fadd_rn(h, v);
    float e = fadd_rn(fsub_rn(h, t), v);   // exact when |h| >= |v|
    l = fadd_rn(l, e);
    h = t;
}
// v -> q0 = f16x2(v), q1 = f16x2(v - f32(q0));  residual ~2^-22 |v| dropped
__device__ __forceinline__ void split1f(float vlo, float vhi, ull neg1,
                                        u32& q0, u32& q1) {
    ull v = packf2(vlo, vhi);
    q0 = cvth2(vlo, vhi);
    ull r1 = fma2v(expandh(q0), neg1, v);      // v - (f32)q0, exact
    float rl, rh; unpackf2(r1, rl, rh);
    q1 = cvth2(rl, rh);
}

// ---- pre-pass: split W once into the SMEM byte-image layout ----
__global__ __launch_bounds__(256)
void wsplit_kernel(const float* __restrict__ gw)
{
    const int c   = blockIdx.x;          // chunk
    const int tid = threadIdx.x;
    const int bn  = tid >> 2;            // expert 0..63
    const int bkt = tid & 3;             // k-tile 0..3
    const float* wp = gw + (size_t)bn * HID + c * KC + bkt * 8;
    const float4 w0 = *(const float4*)(wp);
    const float4 w1 = *(const float4*)(wp + 4);
    const ull NEG1 = packf2(-1.0f, -1.0f);
    u32 s0[4], s1[4];
    split1f(w0.x, w0.y, NEG1, s0[0], s1[0]);
    split1f(w0.z, w0.w, NEG1, s0[1], s1[1]);
    split1f(w1.x, w1.y, NEG1, s0[2], s1[2]);
    split1f(w1.z, w1.w, NEG1, s0[3], s1[3]);
    const int bst = (((bn >> 3) * 4 + bkt) * 8 + ((bn & 7) ^ bkt)) * 16;
    unsigned char* dst = g_wsplit + (size_t)c * 8192 + bst;
    *(uint4*)(dst)        = make_uint4(s0[0], s0[1], s0[2], s0[3]);
    *(uint4*)(dst + 4096) = make_uint4(s1[0], s1[1], s1[2], s1[3]);
}

__global__ __launch_bounds__(NTHR, 1)
void gating_kernel(const float* __restrict__ x,
                   const float* __restrict__ gb,
                   float* __restrict__ out)
{
    extern __shared__ __align__(16) char sm[];
    float* lg  = (float*)sm;                 // logits, reuses stages after loop
    float* gbs = (float*)(sm + SM_GBS);      // bias
    const u32 sb = smem_u32(sm);

    const int tid  = threadIdx.x;
    const int wid  = tid >> 5;
    const int lane = tid & 31;
    const int m0   = blockIdx.x * MT;
    const int half = wid & 1;                // n-half: cols [32*half, 32*half+32)
    const int mw   = wid >> 1;               // row strip: rows [16*mw, 16*mw+16)

    if (tid < NEXP) gbs[tid] = gb[tid];

    const ull NEG1 = packf2(-1.0f, -1.0f);

    // ---- cp.async B mapping: 512 threads x 16B = 8KB stage ----
    const u32 wdoff = (u32)(tid * 16);
    const unsigned char* wsrc = g_wsplit + tid * 16;

    // ---- cp.async A mapping: 2x16B per thread, coalesced, granule-swizzled ----
    //  flat granule i = tid*2 + j (0..1023): row = i>>3 (0..127), g = i&7
    //  dst = AOFF + row*128 + (g ^ (row&7))*16 ; src = x[(m0+row)*HID + c*KC + g*4]
    const int a_r0 = (tid * 2) >> 3;
    const int a_g0 = (tid * 2) & 7;        // j=1 -> g0+1 (same row: 8 | tid*2)
    const float* a_src0 = x + (size_t)(m0 + a_r0) * HID + a_g0 * 4;
    const u32 a_dst0 = (u32)(AOFF + a_r0 * 128 + ((a_g0     ^ (a_r0 & 7)) << 4));
    const u32 a_dst1 = (u32)(AOFF + a_r0 * 128 + (((a_g0+1) ^ (a_r0 & 7)) << 4));

    // ---- LDS A addressing (per-lane fragment source) ----
    const int ar0 = mw * 16 + (lane >> 2);   // CTA-local row
    const int ar1 = ar0 + 8;
    const int cq  = lane & 3;
    const u32 a_in_g = (u32)((cq & 1) << 3); // byte offset within granule (0 or 8)

    // ---- accumulators: 4 n-tiles x 4 regs ----
    float ah[4][4], al[4][4], aM[4][4], aC[4][4];
#pragma unroll
    for (int i = 0; i < 4; i++)
#pragma unroll
        for (int j = 0; j < 4; j++) { ah[i][j] = 0.f; al[i][j] = 0.f; aM[i][j] = 0.f; aC[i][j] = 0.f; }

    // ---- prologue: issue stages 0..PIPE-2 (B + A per stage) ----
#pragma unroll
    for (int p = 0; p < PIPE - 1; p++) {
        const u32 st = sb + p * STAGEB;
        cpasync16(st + wdoff, wsrc + (size_t)p * 8192);
        cpasync16(st + a_dst0, a_src0 + p * KC);
        cpasync16(st + a_dst1, a_src0 + p * KC + 4);
        cp_commit();
    }

    const int g = lane >> 3, rsw = lane & 7;   // ldmatrix lane-group / row

#pragma unroll 2
    for (int c = 0; c < NCH; ++c) {
        // stage c complete (pending <= PIPE-2), then block-wide visibility
        cp_wait<PIPE - 2>();
        __syncthreads();

        // refill freed stage (unconditional commit keeps wait arithmetic exact)
        const int cf = c + PIPE - 1;
        if (cf < NCH) {
            const u32 st = sb + (cf & (PIPE - 1)) * STAGEB;
            cpasync16(st + wdoff, wsrc + (size_t)cf * 8192);
            cpasync16(st + a_dst0, a_src0 + cf * KC);
            cpasync16(st + a_dst1, a_src0 + cf * KC + 4);
        }
        cp_commit();

        // ---- mma phase on stage c%PIPE ----
        const u32 bb = sb + (c & (PIPE - 1)) * STAGEB;
        const u32 ab = bb + AOFF;

#pragma unroll
        for (int s = 0; s < 2; s++) {
            // A fragments from SMEM (granule-swizzled), split in-register
            //  k = cq*2 + s*16 + u*8 -> granule (cq>>1) + s*4 + u*2
            const u32 gs = (u32)((cq >> 1) + s * 4);
            float2 v00 = lds64(ab + (u32)(ar0 * 128) + (((gs    ) ^ (ar0 & 7)) << 4) + a_in_g);
            float2 v10 = lds64(ab + (u32)(ar1 * 128) + (((gs    ) ^ (ar1 & 7)) << 4) + a_in_g);
            float2 v01 = lds64(ab + (u32)(ar0 * 128) + (((gs + 2) ^ (ar0 & 7)) << 4) + a_in_g);
            float2 v11 = lds64(ab + (u32)(ar1 * 128) + (((gs + 2) ^ (ar1 & 7)) << 4) + a_in_g);

            u32 af0[4], af1[4];
            split1f(v00.x, v00.y, NEG1, af0[0], af1[0]);
            split1f(v10.x, v10.y, NEG1, af0[1], af1[1]);
            split1f(v01.x, v01.y, NEG1, af0[2], af1[2]);
            split1f(v11.x, v11.y, NEG1, af0[3], af1[3]);

            const int kt = s * 2 + (g & 1);
            u32 ad[2];
#pragma unroll
            for (int tp = 0; tp < 2; tp++) {
                const int tn = half * 4 + tp * 2 + (g >> 1);
                ad[tp] = bb + (u32)(((tn * 4 + kt) * 8 + (rsw ^ kt)) * 16);
            }

            u32 b[2][4];
            // split0: a0*b0 -> M, a1*b0 -> C
#pragma unroll
            for (int tp = 0; tp < 2; tp++)
                ldsm4(b[tp][0], b[tp][1], b[tp][2], b[tp][3], ad[tp]);
#pragma unroll
            for (int tp = 0; tp < 2; tp++)
#pragma unroll
                for (int t2 = 0; t2 < 2; t2++)
                    mma16816(aM[tp * 2 + t2], af0, b[tp][2 * t2], b[tp][2 * t2 + 1]);
#pragma unroll
            for (int tp = 0; tp < 2; tp++)
#pragma unroll
                for (int t2 = 0; t2 < 2; t2++)
                    mma16816(aC[tp * 2 + t2], af1, b[tp][2 * t2], b[tp][2 * t2 + 1]);

            // split1: a0*b1 -> C
#pragma unroll
            for (int tp = 0; tp < 2; tp++)
                ldsm4(b[tp][0], b[tp][1], b[tp][2], b[tp][3], ad[tp] + 4096);
#pragma unroll
            for (int tp = 0; tp < 2; tp++)
#pragma unroll
                for (int t2 = 0; t2 < 2; t2++)
                    mma16816(aC[tp * 2 + t2], af0, b[tp][2 * t2], b[tp][2 * t2 + 1]);
        }

        // Fast2Sum flush of main accumulator every 2 chunks (K=64)
        if (c & 1) {
#pragma unroll
            for (int i = 0; i < 4; i++)
#pragma unroll
                for (int j = 0; j < 4; j++) {
                    dfadd(ah[i][j], al[i][j], aM[i][j]);
                    aM[i][j] = 0.f;
                }
        }
    }

    __syncthreads();   // all mma reads of stages done before logits overwrite

    // ---- logits = ah + (al + corrections) + bias -> smem ----
    {
        const int row0 = mw * 16 + (lane >> 2);
#pragma unroll
        for (int t = 0; t < 4; t++)
#pragma unroll
            for (int k = 0; k < 4; k++) {
                int row = row0 + ((k >> 1) ? 8 : 0);
                int col = half * 32 + t * 8 + (lane & 3) * 2 + (k & 1);
                float v = fadd_rn(ah[t][k], fadd_rn(al[t][k], aC[t][k]));
                lg[row * NEXP + col] = fadd_rn(v, gbs[col]);
            }
    }
    __syncthreads();

    // ---- top-8 + softmax: one warp per token ----
    const unsigned FULL = 0xffffffffu;
    float* outw = out;
    float* outi = out + (size_t)TOKENS * TOPK;

    for (int t = wid; t < MT; t += 16) {
        float v0 = lg[t * NEXP + lane];
        float v1 = lg[t * NEXP + lane + 32];
        int   i0 = lane, i1 = lane + 32;

        float m = 0.f, ssum = 0.f, myv = 0.f;
        int myi = 0;

#pragma unroll
        for (int s = 0; s < TOPK; s++) {
            float v; int idx;
            if (v0 > v1 || (v0 == v1 && i0 < i1)) { v = v0; idx = i0; }
            else                                  { v = v1; idx = i1; }
#pragma unroll
            for (int off = 16; off > 0; off >>= 1) {
                float ov = __shfl_down_sync(FULL, v,   off);
                int   oi = __shfl_down_sync(FULL, idx, off);
                if (ov > v || (ov == v && oi < idx)) { v = ov; idx = oi; }
            }
            v   = __shfl_sync(FULL, v,   0);
            idx = __shfl_sync(FULL, idx, 0);

            if (s == 0) m = v;               // max (sorted descending)
            ssum += expf(v - m);
            if (lane == s) { myv = v; myi = idx; }

            if (idx == i0) v0 = -FLT_MAX;
            if (idx == i1) v1 = -FLT_MAX;
        }

        if (lane < TOPK) {
            int gidx = (m0 + t) * TOPK + lane;
            outw[gidx] = expf(myv - m) / ssum;
            outi[gidx] = (float)myi;
        }
    }
}

extern "C" void kernel_launch(void* const* d_in, const int* in_sizes, int n_in,
                              void* d_out, int out_size)
{
    const float* x  = (const float*)d_in[0];   // (16384, 4096) f32
    const float* gw = (const float*)d_in[1];   // (64, 4096)    f32
    const float* gb = (const float*)d_in[2];   // (64,)         f32
    float* out = (float*)d_out;                // [weights | indices] as f32

    cudaFuncSetAttribute(gating_kernel,
                         cudaFuncAttributeMaxDynamicSharedMemorySize, SMEM_BYTES);
    wsplit_kernel<<<NCH, 256>>>(gw);
    gating_kernel<<<TOKENS / MT, NTHR, SMEM_BYTES>>>(x, gb, out);
}